// round 1
// baseline (speedup 1.0000x reference)
#include <cuda_runtime.h>

// NCC loss: 9x9 box sums of I, J, I*I, J*J, I*J (zero-padded SAME conv),
// pointwise local correlation cc, mean over all 8*1024*1024 pixels.
//
// Fused single-pass tiled kernel: 32x32 output tile, 40x40 smem staging with
// halo, separable (horizontal-then-vertical) 9-tap sums of 5 channels computed
// entirely in shared memory. Global accumulation via one double atomicAdd per
// block into a __device__ accumulator; tiny zero/finalize kernels bracket it.

#define TILE 32
#define EXPD 40   // TILE + 2*PAD
#define PAD 4
#define IMG_H 1024
#define IMG_W 1024
#define NBATCH 8

__device__ double g_accum;

__global__ void ncc_zero_kernel() {
    g_accum = 0.0;
}

__global__ __launch_bounds__(256) void ncc_main_kernel(
    const float* __restrict__ I, const float* __restrict__ J)
{
    __shared__ float sI[EXPD][EXPD];
    __shared__ float sJ[EXPD][EXPD];
    __shared__ float hI [EXPD][TILE];
    __shared__ float hJ [EXPD][TILE];
    __shared__ float hI2[EXPD][TILE];
    __shared__ float hJ2[EXPD][TILE];
    __shared__ float hIJ[EXPD][TILE];

    const int tid = threadIdx.x;
    const int bx = blockIdx.x * TILE;
    const int by = blockIdx.y * TILE;
    const size_t img_off = (size_t)blockIdx.z * IMG_H * IMG_W;
    const float* Ib = I + img_off;
    const float* Jb = J + img_off;

    // ---- Stage expanded (halo) region into smem; zero outside the image
    // (matches the reference conv's zero padding).
    for (int i = tid; i < EXPD * EXPD; i += 256) {
        int ly = i / EXPD, lx = i - ly * EXPD;
        int gy = by + ly - PAD, gx = bx + lx - PAD;
        float vi = 0.0f, vj = 0.0f;
        if ((unsigned)gy < IMG_H && (unsigned)gx < IMG_W) {
            int g = gy * IMG_W + gx;
            vi = Ib[g];
            vj = Jb[g];
        }
        sI[ly][lx] = vi;
        sJ[ly][lx] = vj;
    }
    __syncthreads();

    // ---- Horizontal 9-tap sums of the 5 channels (products formed on the fly).
    for (int i = tid; i < EXPD * TILE; i += 256) {
        int row = i / TILE, x = i - row * TILE;
        float si = 0.f, sj = 0.f, si2 = 0.f, sj2 = 0.f, sij = 0.f;
        #pragma unroll
        for (int dx = 0; dx < 9; dx++) {
            float a = sI[row][x + dx];
            float c = sJ[row][x + dx];
            si  += a;
            sj  += c;
            si2 = fmaf(a, a, si2);
            sj2 = fmaf(c, c, sj2);
            sij = fmaf(a, c, sij);
        }
        hI [row][x] = si;
        hJ [row][x] = sj;
        hI2[row][x] = si2;
        hJ2[row][x] = sj2;
        hIJ[row][x] = sij;
    }
    __syncthreads();

    // ---- Vertical 9-tap sums + pointwise cc; accumulate per-thread.
    float local = 0.0f;
    for (int i = tid; i < TILE * TILE; i += 256) {
        int oy = i / TILE, ox = i - oy * TILE;
        float si = 0.f, sj = 0.f, si2 = 0.f, sj2 = 0.f, sij = 0.f;
        #pragma unroll
        for (int dy = 0; dy < 9; dy++) {
            si  += hI [oy + dy][ox];
            sj  += hJ [oy + dy][ox];
            si2 += hI2[oy + dy][ox];
            sj2 += hJ2[oy + dy][ox];
            sij += hIJ[oy + dy][ox];
        }
        const float inv81 = 1.0f / 81.0f;
        // cross = IJ_sum - I_sum*J_sum/81 ; var_X = X2_sum - X_sum^2/81
        float cross = fmaf(-si * inv81, sj, sij);
        float iv    = fmaf(-si * inv81, si, si2);
        float jv    = fmaf(-sj * inv81, sj, sj2);
        float cc = (cross * cross) / fmaf(iv, jv, 1e-5f);
        local += cc;
    }

    // ---- Block reduction, then one double atomic per block.
    __shared__ float red[256];
    red[tid] = local;
    __syncthreads();
    #pragma unroll
    for (int s = 128; s >= 32; s >>= 1) {
        if (tid < s) red[tid] += red[tid + s];
        __syncthreads();
    }
    if (tid < 32) {
        float v = red[tid];
        #pragma unroll
        for (int off = 16; off > 0; off >>= 1)
            v += __shfl_down_sync(0xFFFFFFFFu, v, off);
        if (tid == 0)
            atomicAdd(&g_accum, (double)v);
    }
}

__global__ void ncc_final_kernel(float* __restrict__ out) {
    out[0] = (float)(g_accum / (double)((size_t)NBATCH * IMG_H * IMG_W));
}

extern "C" void kernel_launch(void* const* d_in, const int* in_sizes, int n_in,
                              void* d_out, int out_size) {
    const float* I = (const float*)d_in[0];
    const float* J = (const float*)d_in[1];
    float* out = (float*)d_out;

    ncc_zero_kernel<<<1, 1>>>();
    dim3 grid(IMG_W / TILE, IMG_H / TILE, NBATCH);
    ncc_main_kernel<<<grid, 256>>>(I, J);
    ncc_final_kernel<<<1, 1>>>(out);
}

// round 2
// speedup vs baseline: 1.9759x; 1.9759x over previous
#include <cuda_runtime.h>

// NCC loss, sliding-window formulation.
//
// Each block: 256 threads, covers a 512-wide half-row strip, 128 output rows.
// Thread owns 2 adjacent x outputs. For every input row pushed:
//   - row segment (528 floats of I and J, incl. 8-halo) staged to smem
//     (float4 global loads, prefetched one iteration ahead, 1 sync/row),
//   - each thread computes 9-tap horizontal sums of 5 channels
//     (I, J, I*I, J*J, I*J) for its 2 pixels from 5 aligned LDS.64 per array,
//   - vertical 9-row box sums maintained as running sums with a 9-deep
//     register ring (push loop unrolled x9 so ring indices are static),
//   - once 9 rows are in the window, local cc is computed and accumulated.
// Block reduction -> one double atomicAdd per block; tiny zero/final kernels.

#define IMG   1024
#define NB    8
#define HS    128          // output rows per block strip
#define TPB   256
#define NPUSH (HS + 8)     // 136 input-row pushes per strip
#define SEGW  528          // 512 + 2*8 staged floats per row segment

__device__ double g_accum;

__global__ void ncc_zero_kernel() { g_accum = 0.0; }

__device__ __forceinline__ float4 fetch_chunk(const float* __restrict__ I,
                                              const float* __restrict__ J,
                                              int z, int yin, int X0, int c) {
    // c in [0,132): I chunk c ; c in [132,264): J chunk c-132.
    const float* base = (c < 132) ? I : J;
    int cc = (c < 132) ? c : (c - 132);
    int gx0 = X0 - 8 + 4 * cc;     // 4-aligned; OOB chunks are fully OOB
    if ((unsigned)yin < (unsigned)IMG && (unsigned)gx0 <= (unsigned)(IMG - 4)) {
        return *(const float4*)(base + ((size_t)(z * IMG + yin) * IMG + gx0));
    }
    return make_float4(0.f, 0.f, 0.f, 0.f);
}

__global__ __launch_bounds__(TPB, 1) void ncc_main_kernel(
    const float* __restrict__ I, const float* __restrict__ J)
{
    __shared__ __align__(16) float sRow[2][2][SEGW];   // [buf][I/J][x]
    __shared__ float red[TPB];

    const int tid = threadIdx.x;
    const int X0  = blockIdx.x * 512;
    const int Y0  = blockIdx.y * HS;
    const int z   = blockIdx.z;

    // 9-deep ring of horizontal sums + running vertical sums, 5 ch x 2 px.
    float ring[5][2][9];
    float run[5][2];
#pragma unroll
    for (int c = 0; c < 5; c++)
#pragma unroll
        for (int p = 0; p < 2; p++) {
            run[c][p] = 0.f;
#pragma unroll
            for (int s = 0; s < 9; s++) ring[c][p][s] = 0.f;
        }

    float acc = 0.f;

    const int  c0   = tid;
    const int  c1   = 256 + tid;       // only threads 0..7 use this
    const bool hasB = (tid < 8);

    // Prefetch row for push 0 (yin = Y0 - 4).
    float4 pA = fetch_chunk(I, J, z, Y0 - 4, X0, c0);
    float4 pB = hasB ? fetch_chunk(I, J, z, Y0 - 4, X0, c1)
                     : make_float4(0.f, 0.f, 0.f, 0.f);

#pragma unroll 1
    for (int m = 0; m < 16; m++) {
#pragma unroll
        for (int s = 0; s < 9; s++) {
            const int r = m * 9 + s;           // push index; slot = r % 9 = s
            if (r < NPUSH) {
                const int buf = r & 1;
                // ---- store staged row (written into alternate buffer)
                {
                    int arr = (c0 < 132) ? 0 : 1;
                    int cc  = (c0 < 132) ? c0 : (c0 - 132);
                    *(float4*)&sRow[buf][arr][4 * cc] = pA;
                    if (hasB)
                        *(float4*)&sRow[buf][1][4 * (c1 - 132)] = pB;
                }
                __syncthreads();
                // ---- prefetch next row while computing on this one
                if (r + 1 < NPUSH) {
                    pA = fetch_chunk(I, J, z, Y0 - 4 + r + 1, X0, c0);
                    if (hasB) pB = fetch_chunk(I, J, z, Y0 - 4 + r + 1, X0, c1);
                }
                // ---- horizontal 9-tap sums for 2 adjacent pixels
                // window union: sx in [2*tid+4, 2*tid+13] -> float2 idx tid+2..tid+6
                const float2* fI = (const float2*)sRow[buf][0];
                const float2* fJ = (const float2*)sRow[buf][1];
                float2 a0 = fI[tid + 2], a1 = fI[tid + 3], a2 = fI[tid + 4],
                       a3 = fI[tid + 5], a4 = fI[tid + 6];
                float2 b0 = fJ[tid + 2], b1 = fJ[tid + 3], b2 = fJ[tid + 4],
                       b3 = fJ[tid + 5], b4 = fJ[tid + 6];
                float vi[10] = {a0.x, a0.y, a1.x, a1.y, a2.x,
                                a2.y, a3.x, a3.y, a4.x, a4.y};
                float vj[10] = {b0.x, b0.y, b1.x, b1.y, b2.x,
                                b2.y, b3.x, b3.y, b4.x, b4.y};
                float mI = 0.f, mJ = 0.f, mI2 = 0.f, mJ2 = 0.f, mIJ = 0.f;
#pragma unroll
                for (int k = 1; k < 9; k++) {     // shared middle (taps 1..8)
                    float x = vi[k], y = vj[k];
                    mI += x; mJ += y;
                    mI2 = fmaf(x, x, mI2);
                    mJ2 = fmaf(y, y, mJ2);
                    mIJ = fmaf(x, y, mIJ);
                }
                float h[5][2];
                h[0][0] = mI + vi[0];                 h[0][1] = mI + vi[9];
                h[1][0] = mJ + vj[0];                 h[1][1] = mJ + vj[9];
                h[2][0] = fmaf(vi[0], vi[0], mI2);    h[2][1] = fmaf(vi[9], vi[9], mI2);
                h[3][0] = fmaf(vj[0], vj[0], mJ2);    h[3][1] = fmaf(vj[9], vj[9], mJ2);
                h[4][0] = fmaf(vi[0], vj[0], mIJ);    h[4][1] = fmaf(vi[9], vj[9], mIJ);
                // ---- sliding vertical window: run += new - oldest; static slot s
#pragma unroll
                for (int c = 0; c < 5; c++)
#pragma unroll
                    for (int p = 0; p < 2; p++) {
                        run[c][p] += h[c][p] - ring[c][p][s];
                        ring[c][p][s] = h[c][p];
                    }
                // ---- emit output row oy = Y0 + (r - 8)
                if (r >= 8) {
                    const float inv81 = 1.0f / 81.0f;
#pragma unroll
                    for (int p = 0; p < 2; p++) {
                        float si = run[0][p], sj = run[1][p];
                        float cross = fmaf(-si * inv81, sj, run[4][p]);
                        float iv    = fmaf(-si * inv81, si, run[2][p]);
                        float jv    = fmaf(-sj * inv81, sj, run[3][p]);
                        acc += __fdividef(cross * cross, fmaf(iv, jv, 1e-5f));
                    }
                }
            }
        }
    }

    // ---- block reduction, one double atomic per block
    red[tid] = acc;
    __syncthreads();
#pragma unroll
    for (int sred = 128; sred >= 32; sred >>= 1) {
        if (tid < sred) red[tid] += red[tid + sred];
        __syncthreads();
    }
    if (tid < 32) {
        float v = red[tid];
#pragma unroll
        for (int off = 16; off > 0; off >>= 1)
            v += __shfl_down_sync(0xFFFFFFFFu, v, off);
        if (tid == 0)
            atomicAdd(&g_accum, (double)v);
    }
}

__global__ void ncc_final_kernel(float* __restrict__ out) {
    out[0] = (float)(g_accum / (double)((size_t)NB * IMG * IMG));
}

extern "C" void kernel_launch(void* const* d_in, const int* in_sizes, int n_in,
                              void* d_out, int out_size) {
    const float* I = (const float*)d_in[0];
    const float* J = (const float*)d_in[1];
    float* out = (float*)d_out;

    ncc_zero_kernel<<<1, 1>>>();
    dim3 grid(2, IMG / HS, NB);
    ncc_main_kernel<<<grid, TPB>>>(I, J);
    ncc_final_kernel<<<1, 1>>>(out);
}

// round 4
// speedup vs baseline: 2.3994x; 1.2143x over previous
#include <cuda_runtime.h>
#include <cuda_fp16.h>

// NCC loss, sliding-window formulation, occupancy-2 version.
//
// Block: 256 threads, 512-wide strip, HS=64 output rows (72 row pushes).
// Thread owns 2 adjacent x outputs. Per input row pushed:
//   - row segment (528 floats of I and J incl. 8-col halo) staged to smem
//     via float4 loads, prefetched one row ahead, double-buffered, 1 sync/row
//   - 9-tap horizontal sums of 5 channels (I, J, I*I, J*J, I*J) from
//     5 aligned LDS.64 per array (products formed in registers)
//   - vertical 9-row sliding sums: 9-deep ring of h values kept as __half2
//     (45 regs instead of 90 -> 2 blocks/SM). run adds/subtracts the SAME
//     rounded value so the window sum has no drift.
//   - emit: per-row the 2 px fractions are combined into one (n,d); groups of
//     4 emit rows share a single rcp.approx (1 MUFU per 8 pixels).
// Per-block partial -> __device__ array; tiny final kernel reduces. 2 launches.

#define IMG   1024
#define NB    8
#define HS    64
#define TPB   256
#define NPUSH (HS + 8)          // 72 = 8 * 9
#define SEGW  528
#define GX    2
#define GY    (IMG / HS)        // 16
#define NBLK  (GX * GY * NB)    // 256

__device__ float g_part[NBLK];

__global__ __launch_bounds__(TPB, 2) void ncc_main_kernel(
    const float* __restrict__ I, const float* __restrict__ J)
{
    __shared__ __align__(16) float sRow[2][2][SEGW];   // [buf][I/J][x]
    __shared__ float warpsum[8];

    const int tid = threadIdx.x;
    const int X0  = blockIdx.x * 512;
    const int Y0  = blockIdx.y * HS;
    const size_t imgoff = (size_t)blockIdx.z * IMG * IMG;

    // ---- per-thread load assignment (hoisted out of the row loop)
    // chunk A: float4 #tid of the 264-float4 (I row ++ J row) segment
    // chunk B: only threads 0..7, float4 #(256+tid) (tail of J row)
    const bool aIsI = tid < 132;
    const int  ccA  = aIsI ? tid : tid - 132;
    const int  gxA  = X0 - 8 + 4 * ccA;
    const bool vA   = (gxA >= 0) && (gxA <= IMG - 4);
    const float* pbaseA = (aIsI ? I : J) + imgoff + gxA;
    const int  chA  = aIsI ? 0 : 1;
    const int  sxA  = 4 * ccA;

    const bool hasB = tid < 8;
    const int  ccB  = (256 + tid) - 132;               // 124..131
    const int  gxB  = X0 - 8 + 4 * ccB;
    const bool vB   = (gxB >= 0) && (gxB <= IMG - 4);
    const float* pbaseB = J + imgoff + gxB;
    const int  sxB  = 4 * ccB;

    // ---- vertical sliding-window state
    __half2 ring[5][9];
    float   run[5][2];
#pragma unroll
    for (int c = 0; c < 5; c++) {
        run[c][0] = 0.f; run[c][1] = 0.f;
#pragma unroll
        for (int s = 0; s < 9; s++) ring[c][s] = __floats2half2_rn(0.f, 0.f);
    }

    float acc = 0.f, gn = 0.f, gd = 1.f;

    // ---- prefetch row r = 0 (yin = Y0 - 4)
    float4 pA = make_float4(0.f, 0.f, 0.f, 0.f);
    float4 pB = make_float4(0.f, 0.f, 0.f, 0.f);
    {
        int yin0 = Y0 - 4;
        if (vA && (unsigned)yin0 < IMG)
            pA = *(const float4*)(pbaseA + (size_t)yin0 * IMG);
        if (hasB && vB && (unsigned)yin0 < IMG)
            pB = *(const float4*)(pbaseB + (size_t)yin0 * IMG);
    }

#pragma unroll 1
    for (int m = 0; m < NPUSH / 9; m++) {
#pragma unroll
        for (int s = 0; s < 9; s++) {
            const int r   = 9 * m + s;         // push index; ring slot == s
            const int buf = r & 1;

            // ---- store staged row into alternate buffer
            *(float4*)&sRow[buf][chA][sxA] = pA;
            if (hasB) *(float4*)&sRow[buf][1][sxB] = pB;
            __syncthreads();

            // ---- prefetch next row
            if (r + 1 < NPUSH) {
                int yin = Y0 - 3 + r;
                pA = make_float4(0.f, 0.f, 0.f, 0.f);
                if (vA && (unsigned)yin < IMG)
                    pA = *(const float4*)(pbaseA + (size_t)yin * IMG);
                if (hasB) {
                    pB = make_float4(0.f, 0.f, 0.f, 0.f);
                    if (vB && (unsigned)yin < IMG)
                        pB = *(const float4*)(pbaseB + (size_t)yin * IMG);
                }
            }

            // ---- horizontal 9-tap sums for 2 adjacent pixels
            const float2* fI = (const float2*)sRow[buf][0];
            const float2* fJ = (const float2*)sRow[buf][1];
            float2 a0 = fI[tid + 2], a1 = fI[tid + 3], a2 = fI[tid + 4],
                   a3 = fI[tid + 5], a4 = fI[tid + 6];
            float2 b0 = fJ[tid + 2], b1 = fJ[tid + 3], b2 = fJ[tid + 4],
                   b3 = fJ[tid + 5], b4 = fJ[tid + 6];
            float vi[10] = {a0.x, a0.y, a1.x, a1.y, a2.x,
                            a2.y, a3.x, a3.y, a4.x, a4.y};
            float vj[10] = {b0.x, b0.y, b1.x, b1.y, b2.x,
                            b2.y, b3.x, b3.y, b4.x, b4.y};
            float mI = 0.f, mJ = 0.f, mI2 = 0.f, mJ2 = 0.f, mIJ = 0.f;
#pragma unroll
            for (int k = 1; k < 9; k++) {       // shared middle taps 1..8
                float x = vi[k], y = vj[k];
                mI += x; mJ += y;
                mI2 = fmaf(x, x, mI2);
                mJ2 = fmaf(y, y, mJ2);
                mIJ = fmaf(x, y, mIJ);
            }
            float h0[5], h1[5];
            h0[0] = mI + vi[0];               h1[0] = mI + vi[9];
            h0[1] = mJ + vj[0];               h1[1] = mJ + vj[9];
            h0[2] = fmaf(vi[0], vi[0], mI2);  h1[2] = fmaf(vi[9], vi[9], mI2);
            h0[3] = fmaf(vj[0], vj[0], mJ2);  h1[3] = fmaf(vj[9], vj[9], mJ2);
            h0[4] = fmaf(vi[0], vj[0], mIJ);  h1[4] = fmaf(vi[9], vj[9], mIJ);

            // ---- sliding vertical window, half2 ring (drift-free: add the
            // rounded value that will be subtracted 9 rows later)
#pragma unroll
            for (int c = 0; c < 5; c++) {
                __half2 hh  = __floats2half2_rn(h0[c], h1[c]);
                float2  hr  = __half22float2(hh);
                float2  old = __half22float2(ring[c][s]);
                ring[c][s]  = hh;
                run[c][0] += hr.x - old.x;
                run[c][1] += hr.y - old.y;
            }

            // ---- emit output row oy = Y0 + (r - 8)
            if (r >= 8) {
                const float inv81 = 1.0f / 81.0f;
                float si, sj, cross, iv, jv;
                si = run[0][0]; sj = run[1][0];
                cross = fmaf(-si * inv81, sj, run[4][0]);
                iv    = fmaf(-si * inv81, si, run[2][0]);
                jv    = fmaf(-sj * inv81, sj, run[3][0]);
                float n0 = cross * cross;
                float d0 = fmaf(iv, jv, 1e-5f);
                si = run[0][1]; sj = run[1][1];
                cross = fmaf(-si * inv81, sj, run[4][1]);
                iv    = fmaf(-si * inv81, si, run[2][1]);
                jv    = fmaf(-sj * inv81, sj, run[3][1]);
                float n1 = cross * cross;
                float d1 = fmaf(iv, jv, 1e-5f);

                // combine 2 px into one fraction, group 4 rows per reciprocal
                float rowN = fmaf(n0, d1, n1 * d0);
                float rowD = d0 * d1;
                int cnt = (r - 8) & 3;
                if (cnt == 0) { gn = rowN; gd = rowD; }
                else          { gn = fmaf(gn, rowD, rowN * gd); gd *= rowD; }
                if (cnt == 3) {
                    float rc;
                    asm("rcp.approx.f32 %0, %1;" : "=f"(rc) : "f"(gd));
                    acc = fmaf(gn, rc, acc);
                }
            }
        }
    }

    // ---- block reduction -> per-block partial
    const int lane = tid & 31, wid = tid >> 5;
#pragma unroll
    for (int off = 16; off > 0; off >>= 1)
        acc += __shfl_down_sync(0xFFFFFFFFu, acc, off);
    if (lane == 0) warpsum[wid] = acc;
    __syncthreads();
    if (wid == 0) {
        float v = (lane < 8) ? warpsum[lane] : 0.f;
#pragma unroll
        for (int off = 4; off > 0; off >>= 1)
            v += __shfl_down_sync(0xFFFFFFFFu, v, off);
        if (lane == 0) {
            int bid = (blockIdx.z * GY + blockIdx.y) * GX + blockIdx.x;
            g_part[bid] = v;
        }
    }
}

__global__ __launch_bounds__(NBLK) void ncc_final_kernel(float* __restrict__ out) {
    __shared__ float warpsum[8];
    const int tid = threadIdx.x, lane = tid & 31, wid = tid >> 5;
    float v = g_part[tid];
#pragma unroll
    for (int off = 16; off > 0; off >>= 1)
        v += __shfl_down_sync(0xFFFFFFFFu, v, off);
    if (lane == 0) warpsum[wid] = v;
    __syncthreads();
    if (wid == 0) {
        float t = (lane < 8) ? warpsum[lane] : 0.f;
#pragma unroll
        for (int off = 4; off > 0; off >>= 1)
            t += __shfl_down_sync(0xFFFFFFFFu, t, off);
        if (lane == 0)
            out[0] = t * (1.0f / (float)((size_t)NB * IMG * IMG));
    }
}

extern "C" void kernel_launch(void* const* d_in, const int* in_sizes, int n_in,
                              void* d_out, int out_size) {
    const float* I = (const float*)d_in[0];
    const float* J = (const float*)d_in[1];
    float* out = (float*)d_out;

    dim3 grid(GX, GY, NB);
    ncc_main_kernel<<<grid, TPB>>>(I, J);
    ncc_final_kernel<<<1, NBLK>>>(out);
}

// round 5
// speedup vs baseline: 2.5136x; 1.0476x over previous
#include <cuda_runtime.h>
#include <cuda_fp16.h>

// NCC loss, sliding-window, warp-private (barrier-free) version.
//
// Block: 256 threads = 8 independent warps. Each warp owns a 64-px-wide,
// HS=64-row strip; thread owns 2 adjacent x outputs. Per input row:
//   - warp stages its own 80-float segments of I and J (incl. x-halo) into
//     warp-private smem (float4 loads prefetched a row ahead, double buffer,
//     __syncwarp only -- NO __syncthreads in the main loop),
//   - 9-tap horizontal sums of 5 channels from 10 LDS.64,
//   - vertical 9-row sliding sums: 9-deep __half2 ring (drift-free: the
//     rounded value added is the value subtracted 9 rows later), running
//     sums updated with packed f32x2 ops,
//   - emit: cc numer/denom for both pixels computed with packed f32x2;
//     2 px combined into one fraction, 4 rows share one rcp.approx
//     (1 MUFU per 8 px).
// Finalize fused: per-block partial -> double atomicAdd + arrival counter;
// the last block writes the mean and resets the accumulators. ONE launch.

#define IMG   1024
#define NB    8
#define HS    64
#define TPB   256
#define NWARP 8
#define NPUSH (HS + 8)       // 72 = 8 * 9
#define SEGF  80             // floats staged per warp-row per array
#define GX    2
#define GY    (IMG / HS)     // 16
#define NBLK  (GX * GY * NB) // 256

typedef unsigned long long ull;

__device__ double        g_accum;   // zero-initialized; reset by last block
__device__ unsigned int  g_cnt;

__device__ __forceinline__ ull pk2(float lo, float hi) {
    ull o;
    asm("mov.b64 %0, {%1, %2};" : "=l"(o)
        : "r"(__float_as_uint(lo)), "r"(__float_as_uint(hi)));
    return o;
}
__device__ __forceinline__ float2 upk2(ull v) {
    unsigned a, b;
    asm("mov.b64 {%0, %1}, %2;" : "=r"(a), "=r"(b) : "l"(v));
    return make_float2(__uint_as_float(a), __uint_as_float(b));
}
#define FADD2(o,a,b)   asm("add.rn.f32x2 %0,%1,%2;"    : "=l"(o) : "l"(a), "l"(b))
#define FMUL2(o,a,b)   asm("mul.rn.f32x2 %0,%1,%2;"    : "=l"(o) : "l"(a), "l"(b))
#define FFMA2(o,a,b,c) asm("fma.rn.f32x2 %0,%1,%2,%3;" : "=l"(o) : "l"(a), "l"(b), "l"(c))

__global__ __launch_bounds__(TPB, 2) void ncc_main_kernel(
    const float* __restrict__ I, const float* __restrict__ J,
    float* __restrict__ out)
{
    __shared__ __align__(16) float sRow[NWARP][2][2][SEGF]; // [warp][buf][I/J][x]
    __shared__ float warpsum[NWARP];

    const int tid  = threadIdx.x;
    const int lane = tid & 31;
    const int w    = tid >> 5;
    const int W0   = blockIdx.x * 512 + w * 64;   // warp x-origin
    const int Y0   = blockIdx.y * HS;
    const size_t imgoff = (size_t)blockIdx.z * IMG * IMG;

    // ---- per-thread load assignment (warp stages 40 float4 chunks/row:
    // chunks 0..19 = I floats [W0-8, W0+72), chunks 20..39 = J same span)
    const bool aIsI = lane < 20;
    const int  ciA  = aIsI ? lane : lane - 20;
    const int  gxA  = W0 - 8 + 4 * ciA;
    const bool vA   = (gxA >= 0) && (gxA <= IMG - 4);
    const float* pbaseA = (aIsI ? I : J) + imgoff + gxA;
    const int  chA  = aIsI ? 0 : 1;
    const int  sxA  = 4 * ciA;

    const bool hasB = lane < 8;                 // chunks 32..39 -> J 12..19
    const int  ciB  = 12 + lane;
    const int  gxB  = W0 - 8 + 4 * ciB;
    const bool vB   = (gxB >= 0) && (gxB <= IMG - 4);
    const float* pbaseB = J + imgoff + gxB;
    const int  sxB  = 4 * ciB;

    // ---- packed constants
    const ull NEG1   = pk2(-1.0f, -1.0f);
    const ull MINV81 = pk2(-1.0f / 81.0f, -1.0f / 81.0f);
    const ull EPS2   = pk2(1e-5f, 1e-5f);

    // ---- vertical sliding-window state (half2 ring, packed f32x2 run)
    __half2 ring[5][9];
    ull run[5];
#pragma unroll
    for (int c = 0; c < 5; c++) {
        run[c] = pk2(0.f, 0.f);
#pragma unroll
        for (int s = 0; s < 9; s++) ring[c][s] = __floats2half2_rn(0.f, 0.f);
    }

    float acc = 0.f, gn = 0.f, gd = 1.f;

    // ---- prefetch row r = 0 (yin = Y0 - 4)
    float4 pA = make_float4(0.f, 0.f, 0.f, 0.f);
    float4 pB = make_float4(0.f, 0.f, 0.f, 0.f);
    {
        int yin0 = Y0 - 4;
        if (vA && (unsigned)yin0 < IMG)
            pA = *(const float4*)(pbaseA + (size_t)yin0 * IMG);
        if (hasB && vB && (unsigned)yin0 < IMG)
            pB = *(const float4*)(pbaseB + (size_t)yin0 * IMG);
    }

#pragma unroll 1
    for (int m = 0; m < NPUSH / 9; m++) {
#pragma unroll
        for (int s = 0; s < 9; s++) {
            const int r   = 9 * m + s;        // push index; ring slot == s
            const int buf = r & 1;

            // ---- store staged row into this warp's alternate buffer
            *(float4*)&sRow[w][buf][chA][sxA] = pA;
            if (hasB) *(float4*)&sRow[w][buf][1][sxB] = pB;
            __syncwarp();

            // ---- prefetch next row
            if (r + 1 < NPUSH) {
                int yin = Y0 - 3 + r;
                pA = make_float4(0.f, 0.f, 0.f, 0.f);
                if (vA && (unsigned)yin < IMG)
                    pA = *(const float4*)(pbaseA + (size_t)yin * IMG);
                if (hasB) {
                    pB = make_float4(0.f, 0.f, 0.f, 0.f);
                    if (vB && (unsigned)yin < IMG)
                        pB = *(const float4*)(pbaseB + (size_t)yin * IMG);
                }
            }

            // ---- horizontal 9-tap sums for 2 adjacent pixels
            // px pair x = W0+2*lane : window floats [x-4, x+5] ->
            // local float2 idx lane+2 .. lane+6 (buffer origin W0-8)
            const float2* fI = (const float2*)sRow[w][buf][0];
            const float2* fJ = (const float2*)sRow[w][buf][1];
            float2 a0 = fI[lane + 2], a1 = fI[lane + 3], a2 = fI[lane + 4],
                   a3 = fI[lane + 5], a4 = fI[lane + 6];
            float2 b0 = fJ[lane + 2], b1 = fJ[lane + 3], b2 = fJ[lane + 4],
                   b3 = fJ[lane + 5], b4 = fJ[lane + 6];
            float vi[10] = {a0.x, a0.y, a1.x, a1.y, a2.x,
                            a2.y, a3.x, a3.y, a4.x, a4.y};
            float vj[10] = {b0.x, b0.y, b1.x, b1.y, b2.x,
                            b2.y, b3.x, b3.y, b4.x, b4.y};
            float mI = 0.f, mJ = 0.f, mI2 = 0.f, mJ2 = 0.f, mIJ = 0.f;
#pragma unroll
            for (int k = 1; k < 9; k++) {     // shared middle taps 1..8
                float x = vi[k], y = vj[k];
                mI += x; mJ += y;
                mI2 = fmaf(x, x, mI2);
                mJ2 = fmaf(y, y, mJ2);
                mIJ = fmaf(x, y, mIJ);
            }
            float h0[5], h1[5];
            h0[0] = mI + vi[0];               h1[0] = mI + vi[9];
            h0[1] = mJ + vj[0];               h1[1] = mJ + vj[9];
            h0[2] = fmaf(vi[0], vi[0], mI2);  h1[2] = fmaf(vi[9], vi[9], mI2);
            h0[3] = fmaf(vj[0], vj[0], mJ2);  h1[3] = fmaf(vj[9], vj[9], mJ2);
            h0[4] = fmaf(vi[0], vj[0], mIJ);  h1[4] = fmaf(vi[9], vj[9], mIJ);

            // ---- sliding vertical window (add rounded value, subtract the
            // same rounded value 9 rows later -> no drift)
#pragma unroll
            for (int c = 0; c < 5; c++) {
                __half2 hh  = __floats2half2_rn(h0[c], h1[c]);
                ull hr = pk2(__low2float(hh),          __high2float(hh));
                ull od = pk2(__low2float(ring[c][s]),  __high2float(ring[c][s]));
                ring[c][s] = hh;
                FADD2(run[c], run[c], hr);
                FFMA2(run[c], od, NEG1, run[c]);
            }

            // ---- emit output row oy = Y0 + (r - 8), both px packed
            if (r >= 8) {
                ull t, u, cross2, iv2, jv2, n2, d2;
                FMUL2(t, run[0], MINV81);            // -si/81
                FFMA2(cross2, t, run[1], run[4]);    // SIJ - si*sj/81
                FFMA2(iv2,    t, run[0], run[2]);    // SI2 - si^2/81
                FMUL2(u, run[1], MINV81);            // -sj/81
                FFMA2(jv2,    u, run[1], run[3]);    // SJ2 - sj^2/81
                FMUL2(n2, cross2, cross2);
                FFMA2(d2, iv2, jv2, EPS2);
                float2 n = upk2(n2), d = upk2(d2);
                float rowN = fmaf(n.x, d.y, n.y * d.x);
                float rowD = d.x * d.y;
                int cnt = (r - 8) & 3;
                if (cnt == 0) { gn = rowN; gd = rowD; }
                else          { gn = fmaf(gn, rowD, rowN * gd); gd *= rowD; }
                if (cnt == 3) {
                    float rc;
                    asm("rcp.approx.f32 %0, %1;" : "=f"(rc) : "f"(gd));
                    acc = fmaf(gn, rc, acc);
                }
            }
        }
    }

    // ---- block reduction
#pragma unroll
    for (int off = 16; off > 0; off >>= 1)
        acc += __shfl_down_sync(0xFFFFFFFFu, acc, off);
    if (lane == 0) warpsum[w] = acc;
    __syncthreads();
    if (tid == 0) {
        float v = 0.f;
#pragma unroll
        for (int i = 0; i < NWARP; i++) v += warpsum[i];
        atomicAdd(&g_accum, (double)v);
        __threadfence();
        unsigned prev = atomicAdd(&g_cnt, 1u);
        if (prev == NBLK - 1) {               // last block finalizes + resets
            double tot = atomicAdd(&g_accum, 0.0);
            out[0] = (float)(tot / (double)((size_t)NB * IMG * IMG));
            g_accum = 0.0;
            g_cnt   = 0u;
        }
    }
}

extern "C" void kernel_launch(void* const* d_in, const int* in_sizes, int n_in,
                              void* d_out, int out_size) {
    const float* I = (const float*)d_in[0];
    const float* J = (const float*)d_in[1];
    float* out = (float*)d_out;

    dim3 grid(GX, GY, NB);
    ncc_main_kernel<<<grid, TPB>>>(I, J, out);
}

// round 6
// speedup vs baseline: 2.5549x; 1.0164x over previous
#include <cuda_runtime.h>
#include <cstdint>

// NCC loss, sliding-window, cp.async-pipelined version.
//
// Block: 256 threads = 8 independent warps; warp owns a 64-px-wide, 64-row
// strip; thread owns 2 adjacent x outputs. Per input row:
//   - row segments (80 floats of I and J incl. x-halo) land in a warp-private
//     4-deep smem staging ring via cp.async.cg 16B with zero-fill for ALL
//     out-of-bounds chunks (branch-free padding); commit_group/wait_group 3
//     keeps loads 3 rows ahead; __syncwarp only, no block barriers.
//   - 9-tap horizontal sums of 5 channels (I, J, I*I, J*J, I*J) from 10
//     LDS.64; products formed in registers.
//   - vertical 9-row sliding sums: fp32 ring lives in SHARED memory
//     (5ch x 9slot x f32x2 per thread); run updated with packed f32x2 ops;
//     drift-free (adds and later subtracts the identical fp32 value).
//   - emit: packed-f32x2 cc numer/denom; 2 px combine into one fraction,
//     4 rows share one rcp.approx (1 MUFU per 8 px).
// Finalize fused: per-block partial -> double atomicAdd + arrival counter;
// last block writes the mean and resets accumulators. ONE launch.

#define IMG   1024
#define NB    8
#define HS    64
#define TPB   256
#define NWARP 8
#define NPUSH (HS + 8)        // 72 = 8 * 9
#define SEGF  80              // floats staged per warp-row per array
#define NBUF  4               // staging ring depth
#define GX    2
#define GY    (IMG / HS)      // 16
#define NBLK  (GX * GY * NB)  // 256

// dynamic smem layout (floats):
//   [0, 5120)            staging: [buf][warp][arr][SEGF]
//   [5120, 5120+23040)   ring:    [slot][ch][tid] as float2
//   [28160, 28168)       warpsum
#define STG_FLOATS  (NBUF * NWARP * 2 * SEGF)     // 5120
#define RING_F2     (9 * 5 * TPB)                 // 11520 float2
#define SMEM_FLOATS (STG_FLOATS + 2 * RING_F2 + 8)
#define SMEM_BYTES  (SMEM_FLOATS * 4)             // 112672

typedef unsigned long long ull;

__device__ double       g_accum;
__device__ unsigned int g_cnt;

__device__ __forceinline__ ull pk2(float lo, float hi) {
    ull o;
    asm("mov.b64 %0, {%1, %2};" : "=l"(o)
        : "r"(__float_as_uint(lo)), "r"(__float_as_uint(hi)));
    return o;
}
__device__ __forceinline__ float2 upk2(ull v) {
    unsigned a, b;
    asm("mov.b64 {%0, %1}, %2;" : "=r"(a), "=r"(b) : "l"(v));
    return make_float2(__uint_as_float(a), __uint_as_float(b));
}
#define FADD2(o,a,b)   asm("add.rn.f32x2 %0,%1,%2;"    : "=l"(o) : "l"(a), "l"(b))
#define FMUL2(o,a,b)   asm("mul.rn.f32x2 %0,%1,%2;"    : "=l"(o) : "l"(a), "l"(b))
#define FFMA2(o,a,b,c) asm("fma.rn.f32x2 %0,%1,%2,%3;" : "=l"(o) : "l"(a), "l"(b), "l"(c))

__device__ __forceinline__ void cp16(uint32_t dst, const float* src, uint32_t sz) {
    asm volatile("cp.async.cg.shared.global [%0], [%1], 16, %2;"
                 :: "r"(dst), "l"(src), "r"(sz));
}
#define CP_COMMIT() asm volatile("cp.async.commit_group;" ::: "memory")
#define CP_WAIT3()  asm volatile("cp.async.wait_group 3;" ::: "memory")

__global__ __launch_bounds__(TPB, 2) void ncc_main_kernel(
    const float* __restrict__ I, const float* __restrict__ J,
    float* __restrict__ out)
{
    extern __shared__ __align__(16) float dyn[];
    float* warpsum = dyn + STG_FLOATS + 2 * RING_F2;

    const int tid  = threadIdx.x;
    const int lane = tid & 31;
    const int w    = tid >> 5;
    const int W0   = blockIdx.x * 512 + w * 64;
    const int Y0   = blockIdx.y * HS;
    const size_t imgoff = (size_t)blockIdx.z * IMG * IMG;

    uint32_t smem_u32;
    {   // 32-bit smem base address
        asm("{ .reg .u64 t; cvta.to.shared.u64 t, %1; cvt.u32.u64 %0, t; }"
            : "=r"(smem_u32) : "l"(dyn));
    }

    // ---- per-thread cp.async chunk assignment (fixed across rows)
    // chunks 0..19 -> I floats [W0-8, W0+72); chunks 20..39 -> J same span.
    const bool aIsI = lane < 20;
    const int  ciA  = aIsI ? lane : lane - 20;
    const int  gxA  = W0 - 8 + 4 * ciA;
    const bool vA   = (gxA >= 0) && (gxA <= IMG - 4);
    const float* pbaseA = (aIsI ? I : J) + imgoff + (vA ? gxA : 0);
    const uint32_t dstA0 = smem_u32 + ((w * 2 + (aIsI ? 0 : 1)) * SEGF + 4 * ciA) * 4;

    const bool hasB = lane < 8;                // chunks 32..39 -> J 12..19
    const int  ciB  = 12 + lane;
    const int  gxB  = W0 - 8 + 4 * ciB;
    const bool vB   = (gxB >= 0) && (gxB <= IMG - 4);
    const float* pbaseB = J + imgoff + (vB ? gxB : 0);
    const uint32_t dstB0 = smem_u32 + ((w * 2 + 1) * SEGF + 4 * ciB) * 4;

    const uint32_t BUFSTRIDE = NWARP * 2 * SEGF * 4;   // 5120 bytes

    // ---- ring base for this thread (float2 units)
    ull* ringT = (ull*)(dyn + STG_FLOATS) + tid;
#pragma unroll
    for (int s = 0; s < 9; s++)
#pragma unroll
        for (int c = 0; c < 5; c++)
            ringT[(s * 5 + c) * TPB] = 0ull;

    // ---- packed constants / running sums
    const ull NEG1   = pk2(-1.0f, -1.0f);
    const ull MINV81 = pk2(-1.0f / 81.0f, -1.0f / 81.0f);
    const ull EPS2   = pk2(1e-5f, 1e-5f);
    ull run[5];
#pragma unroll
    for (int c = 0; c < 5; c++) run[c] = 0ull;

    float acc = 0.f, gn = 0.f, gd = 1.f;

    // ---- stage helper (row push index rr -> input row Y0-4+rr)
    auto stage = [&](int rr) {
        const int yin  = Y0 - 4 + rr;
        const bool yok = (unsigned)yin < (unsigned)IMG;
        const int  yc  = yok ? yin : 0;
        const uint32_t boff = (uint32_t)(rr & (NBUF - 1)) * BUFSTRIDE;
        cp16(dstA0 + boff, pbaseA + (size_t)yc * IMG, (yok && vA) ? 16u : 0u);
        if (hasB)
            cp16(dstB0 + boff, pbaseB + (size_t)yc * IMG, (yok && vB) ? 16u : 0u);
        CP_COMMIT();
    };

    // ---- prologue: fill pipeline 3 deep
    stage(0); stage(1); stage(2);

#pragma unroll 1
    for (int m = 0; m < NPUSH / 9; m++) {
#pragma unroll
        for (int s = 0; s < 9; s++) {
            const int r = 9 * m + s;

            if (r + 3 < NPUSH) stage(r + 3);
            else               CP_COMMIT();
            CP_WAIT3();
            __syncwarp();

            // ---- horizontal 9-tap sums for 2 adjacent pixels
            const int buf = r & (NBUF - 1);
            const float2* fI = (const float2*)(dyn + (buf * NWARP + w) * 2 * SEGF);
            const float2* fJ = fI + SEGF / 2;
            float2 a0 = fI[lane + 2], a1 = fI[lane + 3], a2 = fI[lane + 4],
                   a3 = fI[lane + 5], a4 = fI[lane + 6];
            float2 b0 = fJ[lane + 2], b1 = fJ[lane + 3], b2 = fJ[lane + 4],
                   b3 = fJ[lane + 5], b4 = fJ[lane + 6];
            float vi[10] = {a0.x, a0.y, a1.x, a1.y, a2.x,
                            a2.y, a3.x, a3.y, a4.x, a4.y};
            float vj[10] = {b0.x, b0.y, b1.x, b1.y, b2.x,
                            b2.y, b3.x, b3.y, b4.x, b4.y};
            float mI = 0.f, mJ = 0.f, mI2 = 0.f, mJ2 = 0.f, mIJ = 0.f;
#pragma unroll
            for (int k = 1; k < 9; k++) {      // shared middle taps 1..8
                float x = vi[k], y = vj[k];
                mI += x; mJ += y;
                mI2 = fmaf(x, x, mI2);
                mJ2 = fmaf(y, y, mJ2);
                mIJ = fmaf(x, y, mIJ);
            }
            float h0[5], h1[5];
            h0[0] = mI + vi[0];               h1[0] = mI + vi[9];
            h0[1] = mJ + vj[0];               h1[1] = mJ + vj[9];
            h0[2] = fmaf(vi[0], vi[0], mI2);  h1[2] = fmaf(vi[9], vi[9], mI2);
            h0[3] = fmaf(vj[0], vj[0], mJ2);  h1[3] = fmaf(vj[9], vj[9], mJ2);
            h0[4] = fmaf(vi[0], vj[0], mIJ);  h1[4] = fmaf(vi[9], vj[9], mIJ);

            // ---- fp32 smem ring: run += h ; run -= old (exact cancellation)
#pragma unroll
            for (int c = 0; c < 5; c++) {
                ull* rp  = ringT + (s * 5 + c) * TPB;
                ull  old = *rp;
                ull  h2  = pk2(h0[c], h1[c]);
                *rp = h2;
                FADD2(run[c], run[c], h2);
                FFMA2(run[c], old, NEG1, run[c]);
            }

            // ---- emit output row oy = Y0 + (r - 8), both px packed
            if (r >= 8) {
                ull t, u, cross2, iv2, jv2, n2, d2;
                FMUL2(t, run[0], MINV81);          // -si/81
                FFMA2(cross2, t, run[1], run[4]);  // SIJ - si*sj/81
                FFMA2(iv2,    t, run[0], run[2]);  // SI2 - si^2/81
                FMUL2(u, run[1], MINV81);          // -sj/81
                FFMA2(jv2,    u, run[1], run[3]);  // SJ2 - sj^2/81
                FMUL2(n2, cross2, cross2);
                FFMA2(d2, iv2, jv2, EPS2);
                float2 n = upk2(n2), d = upk2(d2);
                float rowN = fmaf(n.x, d.y, n.y * d.x);
                float rowD = d.x * d.y;
                int cnt = (r - 8) & 3;
                if (cnt == 0) { gn = rowN; gd = rowD; }
                else          { gn = fmaf(gn, rowD, rowN * gd); gd *= rowD; }
                if (cnt == 3) {
                    float rc;
                    asm("rcp.approx.f32 %0, %1;" : "=f"(rc) : "f"(gd));
                    acc = fmaf(gn, rc, acc);
                }
            }
        }
    }

    // ---- block reduction + fused finalize
#pragma unroll
    for (int off = 16; off > 0; off >>= 1)
        acc += __shfl_down_sync(0xFFFFFFFFu, acc, off);
    if (lane == 0) warpsum[w] = acc;
    __syncthreads();
    if (tid == 0) {
        float v = 0.f;
#pragma unroll
        for (int i = 0; i < NWARP; i++) v += warpsum[i];
        atomicAdd(&g_accum, (double)v);
        __threadfence();
        unsigned prev = atomicAdd(&g_cnt, 1u);
        if (prev == NBLK - 1) {              // last block finalizes + resets
            double tot = atomicAdd(&g_accum, 0.0);
            out[0] = (float)(tot / (double)((size_t)NB * IMG * IMG));
            g_accum = 0.0;
            g_cnt   = 0u;
        }
    }
}

extern "C" void kernel_launch(void* const* d_in, const int* in_sizes, int n_in,
                              void* d_out, int out_size) {
    const float* I = (const float*)d_in[0];
    const float* J = (const float*)d_in[1];
    float* out = (float*)d_out;

    cudaFuncSetAttribute(ncc_main_kernel,
                         cudaFuncAttributeMaxDynamicSharedMemorySize, SMEM_BYTES);
    dim3 grid(GX, GY, NB);
    ncc_main_kernel<<<grid, TPB, SMEM_BYTES>>>(I, J, out);
}